// round 5
// baseline (speedup 1.0000x reference)
#include <cuda_runtime.h>

// Problem constants
#define BB   4
#define HH   8
#define LL   1024
#define DD   64
#define VV   1027          // 2*513+1 relative positions
#define MAXREL 513
#define MTOT (BB*HH*LL)    // 32768 rows
#define SS   1028          // padded row stride for S/T scratch
#define OUT_ELEMS (MTOT*DD)

// Scratch. g_S holds S = Q@EK^T, later reused for T (weight bins). +64 pad so
// unguarded tile loads past a row end stay in-bounds (pad is zero-init).
__device__ float g_S[(size_t)MTOT * SS + 64];
__device__ float g_kT[(size_t)BB * HH * DD * LL];   // [bh][d][y]
__device__ float g_ekT[(size_t)DD * SS + 64];       // [d][j], stride SS, zero-padded

typedef unsigned long long ull;

// ---- packed f32x2 helpers: 128 FMA/cyc/SM on sm_103a ----
__device__ __forceinline__ void ffma2(ull &acc, ull a, ull b) {
    asm volatile("fma.rn.f32x2 %0, %1, %2, %0;" : "+l"(acc) : "l"(a), "l"(b));
}
__device__ __forceinline__ ull bcast2(float x) {
    ull r; asm("mov.b64 %0, {%1, %1};" : "=l"(r) : "f"(x)); return r;
}
__device__ __forceinline__ float2 unpack2(ull v) {
    float2 f; asm("mov.b64 {%0, %1}, %2;" : "=f"(f.x), "=f"(f.y) : "l"(v)); return f;
}

// ============================================================
// Unified GEMM building block: 64(m) x 64(n) block tile, K-tile 32,
// 128 threads, 4x8 thread tile.
// As: swizzled m-major [64][32]: float4 column (k4 ^ (mm>>2)) & 7
//     -> conflict-free LDS.128 in the MMA inner loop.
// Bs: [k][n] = [32][64] direct (n contiguous, 64-bit pair loads).
// ============================================================
__device__ __forceinline__ void loadA(const float* __restrict__ src, int lda,
                                      float* __restrict__ As, int tid) {
#pragma unroll
    for (int i = 0; i < 4; ++i) {
        int f  = tid + i * 128;     // 0..511
        int mm = f >> 3;            // 0..63
        int k4 = f & 7;             // 0..7
        float4 v = *reinterpret_cast<const float4*>(src + (size_t)mm * lda + k4 * 4);
        *reinterpret_cast<float4*>(&As[mm * 32 + ((k4 ^ (mm >> 2)) & 7) * 4]) = v;
    }
}

__device__ __forceinline__ void loadB(const float* __restrict__ src, int ldb,
                                      float* __restrict__ Bs, int tid) {
#pragma unroll
    for (int i = 0; i < 4; ++i) {
        int f  = tid + i * 128;
        int kl = f >> 4;            // 0..31
        int nn = (f & 15) * 4;      // 0..60
        *reinterpret_cast<float4*>(&Bs[kl * 64 + nn]) =
            *reinterpret_cast<const float4*>(src + (size_t)kl * ldb + nn);
    }
}

__device__ __forceinline__ void loadB_guard(const float* __restrict__ src, int ldb,
                                            int rows_valid, float* __restrict__ Bs,
                                            int tid) {
#pragma unroll
    for (int i = 0; i < 4; ++i) {
        int f  = tid + i * 128;
        int kl = f >> 4;
        int nn = (f & 15) * 4;
        float4 v = make_float4(0.f, 0.f, 0.f, 0.f);
        if (kl < rows_valid)
            v = *reinterpret_cast<const float4*>(src + (size_t)kl * ldb + nn);
        *reinterpret_cast<float4*>(&Bs[kl * 64 + nn]) = v;
    }
}

__device__ __forceinline__ void mma32(const float* __restrict__ As,
                                      const float* __restrict__ Bs,
                                      ull (&acc)[4][4], int ty, int col0) {
    const int row0 = ty * 4;
#pragma unroll
    for (int k4 = 0; k4 < 8; ++k4) {
        const int swc = ((k4 ^ ty) & 7) * 4;   // (row>>2)==ty for all 4 rows
        float4 a[4];
#pragma unroll
        for (int r = 0; r < 4; ++r)
            a[r] = *reinterpret_cast<const float4*>(&As[(row0 + r) * 32 + swc]);
#pragma unroll
        for (int u = 0; u < 4; ++u) {
            const ull* bp = reinterpret_cast<const ull*>(&Bs[(k4 * 4 + u) * 64 + col0]);
            ull b0 = bp[0], b1 = bp[1], b2 = bp[2], b3 = bp[3];
#pragma unroll
            for (int r = 0; r < 4; ++r) {
                ull ap = bcast2(reinterpret_cast<const float*>(&a[r])[u]);
                ffma2(acc[r][0], ap, b0);
                ffma2(acc[r][1], ap, b1);
                ffma2(acc[r][2], ap, b2);
                ffma2(acc[r][3], ap, b3);
            }
        }
    }
}

// ============================================================
// Transpose kernels (run once, ~3us): K -> kT [bh][d][y], EK -> ekT [d][j]
// ============================================================
__global__ void __launch_bounds__(256) kT_kernel(const float* __restrict__ k) {
    __shared__ float tile[32][33];
    const int bh = blockIdx.z;
    const int y0 = blockIdx.x * 32, d0 = blockIdx.y * 32;
    const int tx = threadIdx.x, tyy = threadIdx.y;
    const float* kb = k + (size_t)bh * LL * DD;
#pragma unroll
    for (int i = tyy; i < 32; i += 8)
        tile[i][tx] = kb[(size_t)(y0 + i) * DD + d0 + tx];
    __syncthreads();
    float* kTb = g_kT + (size_t)bh * DD * LL;
#pragma unroll
    for (int i = tyy; i < 32; i += 8)
        kTb[(size_t)(d0 + i) * LL + y0 + tx] = tile[tx][i];
}

__global__ void __launch_bounds__(256) ekT_kernel(const float* __restrict__ ek) {
    __shared__ float tile[32][33];
    const int j0 = blockIdx.x * 32, d0 = blockIdx.y * 32;
    const int tx = threadIdx.x, tyy = threadIdx.y;
#pragma unroll
    for (int i = tyy; i < 32; i += 8) {
        int j = j0 + i;
        tile[i][tx] = (j < VV) ? ek[(size_t)j * DD + d0 + tx] : 0.f;
    }
    __syncthreads();
#pragma unroll
    for (int i = tyy; i < 32; i += 8) {
        int j = j0 + tx;
        if (j < VV) g_ekT[(size_t)(d0 + i) * SS + j] = tile[tx][i];
    }
}

// ============================================================
// Kernel 1: S[m, j] = sum_d Q[m, d] * EK[j, d]   (M=32768, N=1027, K=64)
// ============================================================
__global__ void __launch_bounds__(128) s_gemm_kernel(const float* __restrict__ q) {
    __shared__ float As[64 * 32];
    __shared__ float Bs[32 * 64];
    const int tid = threadIdx.x;
    const int m0 = blockIdx.x * 64;
    const int n0 = blockIdx.y * 64;
    const int tx = tid & 7, ty = tid >> 3;

    ull acc[4][4];
#pragma unroll
    for (int r = 0; r < 4; ++r)
#pragma unroll
        for (int p = 0; p < 4; ++p) acc[r][p] = 0ULL;

#pragma unroll
    for (int kt = 0; kt < 2; ++kt) {
        loadA(q + (size_t)m0 * DD + kt * 32, DD, As, tid);
        loadB(g_ekT + (size_t)kt * 32 * SS + n0, SS, Bs, tid);
        __syncthreads();
        mma32(As, Bs, acc, ty, tx * 8);
        __syncthreads();
    }

#pragma unroll
    for (int r = 0; r < 4; ++r) {
        int row = m0 + ty * 4 + r;
        float* srow = g_S + (size_t)row * SS;
#pragma unroll
        for (int p = 0; p < 4; ++p) {
            float2 vv = unpack2(acc[r][p]);
            int c0 = n0 + tx * 8 + p * 2;
            if (c0     < VV) srow[c0]     = vv.x;
            if (c0 + 1 < VV) srow[c0 + 1] = vv.y;
        }
    }
}

// ============================================================
// Kernel 2: W[bh, x, y] = Q.K^T + bias + S[bh*L+x, clip(y-x)+513]
// ============================================================
__global__ void __launch_bounds__(128) qk_kernel(const float* __restrict__ q,
                                                 const float* __restrict__ bias,
                                                 float* __restrict__ W) {
    __shared__ float As[64 * 32];
    __shared__ float Bs[32 * 64];
    const int tid = threadIdx.x;
    const int bh = blockIdx.z;
    const int m0 = blockIdx.x * 64;
    const int n0 = blockIdx.y * 64;
    const int tx = tid & 7, ty = tid >> 3;
    const float* qb  = q    + (size_t)bh * LL * DD;
    const float* kTb = g_kT + (size_t)bh * DD * LL;

    ull acc[4][4];
#pragma unroll
    for (int r = 0; r < 4; ++r)
#pragma unroll
        for (int p = 0; p < 4; ++p) acc[r][p] = 0ULL;

#pragma unroll
    for (int kt = 0; kt < 2; ++kt) {
        loadA(qb + (size_t)m0 * DD + kt * 32, DD, As, tid);
        loadB(kTb + (size_t)kt * 32 * LL + n0, LL, Bs, tid);
        __syncthreads();
        mma32(As, Bs, acc, ty, tx * 8);
        __syncthreads();
    }

    const float* biasb = bias + (size_t)bh * LL * LL;
    float*       Wb    = W    + (size_t)bh * LL * LL;
    const float* Sb    = g_S  + (size_t)bh * LL * SS;

#pragma unroll
    for (int r = 0; r < 4; ++r) {
        int row = m0 + ty * 4 + r;
        const float* srow = Sb    + (size_t)row * SS;
        const float* brow = biasb + (size_t)row * LL;
        float*       wrow = Wb    + (size_t)row * LL;
#pragma unroll
        for (int p = 0; p < 4; ++p) {
            float2 vv = unpack2(acc[r][p]);
            int c0 = n0 + tx * 8 + p * 2;
            int j0 = c0 - row;     j0 = min(max(j0, -MAXREL), MAXREL) + MAXREL;
            int j1 = c0 + 1 - row; j1 = min(max(j1, -MAXREL), MAXREL) + MAXREL;
            wrow[c0]     = vv.x + brow[c0]     + srow[j0];
            wrow[c0 + 1] = vv.y + brow[c0 + 1] + srow[j1];
        }
    }
}

// ============================================================
// Kernel 3 (fused): in-place row softmax + build T bins in one pass.
// ============================================================
__global__ void __launch_bounds__(256) softmax_tbuild_kernel(float* __restrict__ W) {
    const int m = blockIdx.x;
    const int rowx = m & (LL - 1);
    const int tid = threadIdx.x;
    float4* row = reinterpret_cast<float4*>(W + (size_t)m * LL);
    float* t = g_S + (size_t)m * SS;

    float4 x = row[tid];

    float mx = fmaxf(fmaxf(x.x, x.y), fmaxf(x.z, x.w));
#pragma unroll
    for (int o = 16; o; o >>= 1) mx = fmaxf(mx, __shfl_xor_sync(0xffffffffu, mx, o));
    __shared__ float redm[8];
    __shared__ float reds[8];
    if ((tid & 31) == 0) redm[tid >> 5] = mx;
    __syncthreads();
    float m2 = redm[0];
#pragma unroll
    for (int i = 1; i < 8; ++i) m2 = fmaxf(m2, redm[i]);

    x.x = __expf(x.x - m2);
    x.y = __expf(x.y - m2);
    x.z = __expf(x.z - m2);
    x.w = __expf(x.w - m2);
    float s = (x.x + x.y) + (x.z + x.w);
#pragma unroll
    for (int o = 16; o; o >>= 1) s += __shfl_xor_sync(0xffffffffu, s, o);
    if ((tid & 31) == 0) reds[tid >> 5] = s;
    __syncthreads();
    float st = reds[0];
#pragma unroll
    for (int i = 1; i < 8; ++i) st += reds[i];

    float inv = 1.0f / st;
    x.x *= inv; x.y *= inv; x.z *= inv; x.w *= inv;
    row[tid] = x;

    // T build: zero-fill invalid interior bins (disjoint from scatter set)
    for (int j = 1 + tid; j <= 1025; j += 256) {
        int y = rowx + j - MAXREL;
        if ((unsigned)y >= (unsigned)LL) t[j] = 0.f;
    }
    const float vals[4] = {x.x, x.y, x.z, x.w};
    float sp = 0.f, sq = 0.f;
    const int y0 = tid * 4;
#pragma unroll
    for (int u = 0; u < 4; ++u) {
        int dist = y0 + u - rowx;
        if (dist <= -MAXREL)      sp += vals[u];
        else if (dist >= MAXREL)  sq += vals[u];
        else                      t[dist + MAXREL] = vals[u];
    }
#pragma unroll
    for (int o = 16; o; o >>= 1) {
        sp += __shfl_xor_sync(0xffffffffu, sp, o);
        sq += __shfl_xor_sync(0xffffffffu, sq, o);
    }
    __shared__ float r1[8];
    __shared__ float r2[8];
    if ((tid & 31) == 0) { r1[tid >> 5] = sp; r2[tid >> 5] = sq; }
    __syncthreads();
    if (tid == 0) {
        float a = 0.f, b = 0.f;
#pragma unroll
        for (int i = 0; i < 8; ++i) { a += r1[i]; b += r2[i]; }
        t[0] = a;
        t[1026] = b;
        t[1027] = 0.f;   // keep pad slot clean for unguarded tile loads
    }
}

// ============================================================
// Kernel 4: out = W @ V + T @ EV   (per bh: M=1024, N=64, K=1024 then 1027)
// Double-buffered smem ping-pong: one barrier per K-iter, loads of tile
// kt+1 overlap the MMA of tile kt.
// ============================================================
__device__ __forceinline__ void out_load_tile(int kt,
                                              const float* __restrict__ Wb,
                                              const float* __restrict__ vb,
                                              const float* __restrict__ Tb,
                                              const float* __restrict__ ev,
                                              int m0, int tid,
                                              float* __restrict__ As,
                                              float* __restrict__ Bs) {
    if (kt < 32) {
        const int koff = kt * 32;
        loadA(Wb + (size_t)m0 * LL + koff, LL, As, tid);
        loadB(vb + (size_t)koff * DD, DD, Bs, tid);
    } else {
        const int koff = (kt - 32) * 32;
        // T rows: unguarded (row pad + array pad are zero; the matching B
        // rows beyond VV are zero-filled so spill terms vanish)
        loadA(Tb + koff, SS, As, tid);
        loadB_guard(ev + (size_t)koff * DD, DD, VV - koff, Bs, tid);
    }
}

__global__ void __launch_bounds__(128) out_kernel(const float* __restrict__ W,
                                                  const float* __restrict__ v,
                                                  const float* __restrict__ ev,
                                                  float* __restrict__ out) {
    __shared__ float As[2][64 * 32];
    __shared__ float Bs[2][32 * 64];
    const int tid = threadIdx.x;
    const int bh = blockIdx.y;
    const int m0 = blockIdx.x * 64;
    const int tx = tid & 7, ty = tid >> 3;
    const float* Wb = W + (size_t)bh * LL * LL;
    const float* vb = v + (size_t)bh * LL * DD;
    const float* Tb = g_S + ((size_t)bh * LL + m0) * SS;

    ull acc[4][4];
#pragma unroll
    for (int r = 0; r < 4; ++r)
#pragma unroll
        for (int p = 0; p < 4; ++p) acc[r][p] = 0ULL;

    out_load_tile(0, Wb, vb, Tb, ev, m0, tid, As[0], Bs[0]);
    __syncthreads();

    for (int kt = 0; kt < 65; ++kt) {
        const int cur = kt & 1;
        if (kt + 1 < 65)
            out_load_tile(kt + 1, Wb, vb, Tb, ev, m0, tid, As[cur ^ 1], Bs[cur ^ 1]);
        mma32(As[cur], Bs[cur], acc, ty, tx * 8);
        __syncthreads();   // next-tile writes visible; cur buffer free for kt+2
    }

#pragma unroll
    for (int r = 0; r < 4; ++r) {
        int row = m0 + ty * 4 + r;
        float* orow = out + (size_t)(bh * LL + row) * DD;
#pragma unroll
        for (int p = 0; p < 4; ++p) {
            float2 vv = unpack2(acc[r][p]);
            int c0 = tx * 8 + p * 2;
            orow[c0]     = vv.x;
            orow[c0 + 1] = vv.y;
        }
    }
}

// ============================================================
extern "C" void kernel_launch(void* const* d_in, const int* in_sizes, int n_in,
                              void* d_out, int out_size) {
    const float* q    = (const float*)d_in[0];
    const float* k    = (const float*)d_in[1];
    const float* v    = (const float*)d_in[2];
    const float* bias = (const float*)d_in[3];
    const float* ek   = (const float*)d_in[4];
    const float* ev   = (const float*)d_in[5];
    float* out = (float*)d_out;              // (B,H,L,D) first
    float* W   = out + OUT_ELEMS;            // then weights (B,H,L,L)

    kT_kernel <<<dim3(32, 2, 32), dim3(32, 8)>>>(k);
    ekT_kernel<<<dim3(33, 2),     dim3(32, 8)>>>(ek);
    s_gemm_kernel<<<dim3(512, 17), 128>>>(q);
    qk_kernel<<<dim3(16, 16, 32), 128>>>(q, bias, W);
    softmax_tbuild_kernel<<<MTOT, 256>>>(W);
    out_kernel<<<dim3(16, 32), 128>>>(W, v, ev, out);
}